// round 1
// baseline (speedup 1.0000x reference)
#include <cuda_runtime.h>
#include <cstddef>

// DCTFeatureModel: the whole model is linear up to LeakyReLU.
// feat[b,s,o] = sum_{t,ij} xc[b,s,t,ij] * Veff[s,o,t,ij] + bias[s,o]
//   xc[b,s,t,ij]   = sum_c x[b, s*256 + c*32 + t, ij]
//   Veff[s,o,t,i,j]= (1/8) sum_{f,p,q} Ct[f,t] Cs[p,i] Cs[q,j] W[s,o,f,p,q]
// out[b, s*64+o] = leaky_relu(feat)
//
// Kernels:
//   prep_kernel: Veff (separable DCT transform of W) -> g_veff[s][t][ij][o]
//   main_kernel: fused c-reduction + GEMM, k-split into 8 partials
//   epi_kernel : sum partials + bias + LeakyReLU

#define NSW 2
#define NF 64
#define NDCT 32
#define HW2 64          // 8*8
#define KTOT 2048       // NDCT * HW2
#define BATCH 1024
#define KSPLIT 8
#define MTILES 16       // 1024 / 64
#define BTILE 64

__device__ float g_veff[NSW * NDCT * HW2 * NF];      // [s][t][ij][o], 1 MB
__device__ float g_part[KSPLIT * BATCH * NSW * NF];  // 4 MB

// ---------------------------------------------------------------------------
// prep: Veff[s,o,t,i,j] = (1/8) sum_{f,p,q} Ct[f,t] Cs[p,i] Cs[q,j] W[s,o,f,p,q]
// one CTA per (s,o)
// ---------------------------------------------------------------------------
__global__ void __launch_bounds__(256) prep_kernel(const float* __restrict__ W) {
    __shared__ float A[2048];
    __shared__ float Bf[2048];
    __shared__ float Ct[1024];   // Ct[t*32 + f] = 2 cos(pi*(2t+1)*f/64)
    __shared__ float Cs[64];     // Cs[i*8 + p]  = 2 cos(pi*(2i+1)*p/16)

    const int tid = threadIdx.x;
    const int s = blockIdx.x >> 6;
    const int o = blockIdx.x & 63;

#pragma unroll
    for (int r = 0; r < 4; ++r) {
        int idx = tid + 256 * r;
        int t = idx >> 5, f = idx & 31;
        Ct[idx] = 2.0f * cospif((float)((2 * t + 1) * f) / 64.0f);
    }
    if (tid < 64) {
        int i = tid >> 3, p = tid & 7;
        Cs[tid] = 2.0f * cospif((float)((2 * i + 1) * p) / 16.0f);
    }
    const float* Wso = W + ((size_t)(s * 64 + o) << 11);
#pragma unroll
    for (int r = 0; r < 8; ++r) A[tid + 256 * r] = Wso[tid + 256 * r];
    __syncthreads();

    // stage 1: freq f -> time t   Bf[t*64+pq] = sum_f Ct[t,f] * A[f*64+pq]
#pragma unroll
    for (int r = 0; r < 8; ++r) {
        int idx = tid + 256 * r;
        int t = idx >> 6, pq = idx & 63;
        float acc = 0.0f;
#pragma unroll
        for (int f = 0; f < 32; ++f) acc = fmaf(Ct[t * 32 + f], A[f * 64 + pq], acc);
        Bf[idx] = acc;
    }
    __syncthreads();

    // stage 2: p -> i   A[t*64 + i*8 + q] = sum_p Cs[i,p] * Bf[t*64 + p*8 + q]
#pragma unroll
    for (int r = 0; r < 8; ++r) {
        int idx = tid + 256 * r;
        int t = idx >> 6, i = (idx >> 3) & 7, q = idx & 7;
        float acc = 0.0f;
#pragma unroll
        for (int p = 0; p < 8; ++p) acc = fmaf(Cs[i * 8 + p], Bf[t * 64 + p * 8 + q], acc);
        __syncthreads();  // noop-safe? No: need all reads of Bf before overwriting A? A!=Bf, safe.
        A[idx] = acc;
    }
    __syncthreads();

    // stage 3: q -> j, scale 1/8, write g_veff[s][t][ij][o]
#pragma unroll
    for (int r = 0; r < 8; ++r) {
        int idx = tid + 256 * r;
        int t = idx >> 6, i = (idx >> 3) & 7, j = idx & 7;
        float acc = 0.0f;
#pragma unroll
        for (int q = 0; q < 8; ++q) acc = fmaf(Cs[j * 8 + q], A[t * 64 + i * 8 + q], acc);
        g_veff[(((s * 32 + t) << 6) + (i * 8 + j)) * 64 + o] = 0.125f * acc;
    }
}

// ---------------------------------------------------------------------------
// main: grid = NSW * MTILES * KSPLIT = 256 CTAs, 256 threads.
// CTA computes partial GEMM for 64 batches x 64 outputs over K = 256 (4 t's),
// with the c-reduction of x fused into the smem load.
// ---------------------------------------------------------------------------
__global__ void __launch_bounds__(256) main_kernel(const float* __restrict__ x) {
    __shared__ __align__(16) float xs[32][65];  // [ij_local][b], padded
    __shared__ __align__(16) float ws[32][64];  // [ij_local][o]

    const int bx = blockIdx.x;
    const int ks = bx & 7;
    const int mt = (bx >> 3) & 15;
    const int s  = bx >> 7;

    const int tid = threadIdx.x;
    const int tx = tid & 15, ty = tid >> 4;   // compute mapping
    const int ijl = tid & 31, bg = tid >> 5;  // load mapping

    float acc[4][4] = {};

    // x[b][time][ij]: b stride 32768 floats, time stride 64, s base = s*256*64
    const float* xbase = x + (size_t)(mt * 64 + bg * 8) * 32768 + (size_t)s * 16384;

#pragma unroll 1
    for (int tt = 0; tt < 4; ++tt) {
        const int t = ks * 4 + tt;
#pragma unroll 1
        for (int h = 0; h < 2; ++h) {
            __syncthreads();
            // ---- load + c-reduce x chunk: xs[ijl][b] for 64 b, 32 ij ----
#pragma unroll
            for (int bb = 0; bb < 8; ++bb) {
                const float* p = xbase + (size_t)bb * 32768 + t * 64 + h * 32 + ijl;
                float a = 0.0f;
#pragma unroll
                for (int c = 0; c < 8; ++c) a += p[c * 2048];
                xs[ijl][bg * 8 + bb] = a;
            }
            // ---- load Veff chunk: contiguous [ij][o] 2048 floats ----
            {
                const float4* wsrc =
                    (const float4*)(g_veff + ((((s * 32 + t) << 6) + h * 32) << 6));
                float4* wdst = (float4*)&ws[0][0];
                wdst[tid] = wsrc[tid];
                wdst[tid + 256] = wsrc[tid + 256];
            }
            __syncthreads();
            // ---- inner product over 32 k's ----
#pragma unroll
            for (int k = 0; k < 32; ++k) {
                float wv[4], xv[4];
#pragma unroll
                for (int j = 0; j < 4; ++j) wv[j] = ws[k][tx + 16 * j];
#pragma unroll
                for (int i = 0; i < 4; ++i) xv[i] = xs[k][ty + 16 * i];
#pragma unroll
                for (int i = 0; i < 4; ++i)
#pragma unroll
                    for (int j = 0; j < 4; ++j) acc[i][j] = fmaf(xv[i], wv[j], acc[i][j]);
            }
        }
    }

    // ---- write partials: g_part[ks][b][s*64+o] ----
    const int b0 = mt * 64;
#pragma unroll
    for (int i = 0; i < 4; ++i) {
        const int b = b0 + ty + 16 * i;
        float* dst = g_part + ((size_t)ks << 17) + (size_t)b * 128 + s * 64 + tx;
#pragma unroll
        for (int j = 0; j < 4; ++j) dst[16 * j] = acc[i][j];
    }
}

// ---------------------------------------------------------------------------
// epilogue: sum KSPLIT partials + bias, LeakyReLU
// ---------------------------------------------------------------------------
__global__ void __launch_bounds__(256) epi_kernel(const float* __restrict__ bias,
                                                  float* __restrict__ out) {
    const int idx = blockIdx.x * 256 + threadIdx.x;  // < 131072
    const int so = idx & 127;
    float a = bias[so];
#pragma unroll
    for (int k = 0; k < KSPLIT; ++k) a += g_part[((size_t)k << 17) + idx];
    out[idx] = (a >= 0.0f) ? a : 0.02f * a;
}

// ---------------------------------------------------------------------------
extern "C" void kernel_launch(void* const* d_in, const int* in_sizes, int n_in,
                              void* d_out, int out_size) {
    const float* x = nullptr;
    const float* W = nullptr;
    const float* bias = nullptr;
    for (int i = 0; i < n_in; ++i) {
        if (in_sizes[i] == 1024 * 512 * 64) x = (const float*)d_in[i];
        else if (in_sizes[i] == NSW * NF * NDCT * HW2) W = (const float*)d_in[i];
        else if (in_sizes[i] == NSW * NF) bias = (const float*)d_in[i];
    }
    if (!x) x = (const float*)d_in[0];
    if (!W) W = (const float*)d_in[1];
    if (!bias) bias = (const float*)d_in[2];

    prep_kernel<<<NSW * NF, 256>>>(W);
    main_kernel<<<NSW * MTILES * KSPLIT, 256>>>(x);
    epi_kernel<<<(BATCH * NSW * NF) / 256, 256>>>(bias, (float*)d_out);
}

// round 2
// speedup vs baseline: 1.8171x; 1.8171x over previous
#include <cuda_runtime.h>
#include <cstddef>

// DCTFeatureModel — collapsed linear model:
// feat[b,s,o] = sum_{t,ij} xc[b,s,t,ij] * Veff[s,o,t,ij] + bias[s,o]
//   xc[b,s,t,ij]    = sum_c x[b, s*256 + c*32 + t, ij]
//   Veff[s,o,t,i,j] = (1/8) sum_{f,p,q} Ct[f,t] Cs[p,i] Cs[q,j] W[s,o,f,p,q]
// out[b, s*64+o] = leaky_relu(feat)

#define NSW 2
#define NF 64
#define KSPLIT 16   // t split into 16 chunks of 2
#define MTILES 16   // batch split into 16 tiles of 64

__device__ __align__(16) float g_veff[NSW * 32 * 64 * 64];        // [s][t][ij][o], 1 MB
__device__ __align__(16) float g_part[KSPLIT * 1024 * NSW * NF];  // 8 MB

typedef unsigned long long u64;

__device__ __forceinline__ u64 pk2(float a, float b) {
    u64 r; asm("mov.b64 %0,{%1,%2};" : "=l"(r) : "f"(a), "f"(b)); return r;
}
__device__ __forceinline__ float2 up2(u64 a) {
    float2 v; asm("mov.b64 {%0,%1},%2;" : "=f"(v.x), "=f"(v.y) : "l"(a)); return v;
}
__device__ __forceinline__ void fma2(u64& d, u64 a, u64 b) {
    asm("fma.rn.f32x2 %0,%1,%2,%0;" : "+l"(d) : "l"(a), "l"(b));
}
__device__ __forceinline__ u64 add2(u64 a, u64 b) {
    u64 r; asm("add.rn.f32x2 %0,%1,%2;" : "=l"(r) : "l"(a), "l"(b)); return r;
}

// ---------------------------------------------------------------------------
// prep: Veff[s,o,t,i,j] = (1/8) sum_{f,p,q} Ct[f,t] Cs[p,i] Cs[q,j] W[s,o,f,p,q]
// one CTA per (s,o)
// ---------------------------------------------------------------------------
__global__ void __launch_bounds__(256) prep_kernel(const float* __restrict__ W) {
    __shared__ float A[2048];
    __shared__ float Bf[2048];
    __shared__ float Ct[1024];   // Ct[t*32 + f] = 2 cos(pi*(2t+1)*f/64)
    __shared__ float Cs[64];     // Cs[i*8 + p]  = 2 cos(pi*(2i+1)*p/16)

    const int tid = threadIdx.x;
    const int s = blockIdx.x >> 6;
    const int o = blockIdx.x & 63;

#pragma unroll
    for (int r = 0; r < 4; ++r) {
        int idx = tid + 256 * r;
        int t = idx >> 5, f = idx & 31;
        Ct[idx] = 2.0f * cospif((float)((2 * t + 1) * f) / 64.0f);
    }
    if (tid < 64) {
        int i = tid >> 3, p = tid & 7;
        Cs[tid] = 2.0f * cospif((float)((2 * i + 1) * p) / 16.0f);
    }
    const float* Wso = W + ((size_t)(s * 64 + o) << 11);
#pragma unroll
    for (int r = 0; r < 8; ++r) A[tid + 256 * r] = Wso[tid + 256 * r];
    __syncthreads();

    // stage 1: freq f -> time t
#pragma unroll
    for (int r = 0; r < 8; ++r) {
        int idx = tid + 256 * r;
        int t = idx >> 6, pq = idx & 63;
        float acc = 0.0f;
#pragma unroll
        for (int f = 0; f < 32; ++f) acc = fmaf(Ct[t * 32 + f], A[f * 64 + pq], acc);
        Bf[idx] = acc;
    }
    __syncthreads();

    // stage 2: p -> i   (A and Bf are distinct buffers: no barrier needed inside)
#pragma unroll
    for (int r = 0; r < 8; ++r) {
        int idx = tid + 256 * r;
        int t = idx >> 6, i = (idx >> 3) & 7, q = idx & 7;
        float acc = 0.0f;
#pragma unroll
        for (int p = 0; p < 8; ++p) acc = fmaf(Cs[i * 8 + p], Bf[t * 64 + p * 8 + q], acc);
        A[idx] = acc;
    }
    __syncthreads();

    // stage 3: q -> j, scale 1/8, write g_veff[s][t][ij][o]
#pragma unroll
    for (int r = 0; r < 8; ++r) {
        int idx = tid + 256 * r;
        int t = idx >> 6, i = (idx >> 3) & 7, j = idx & 7;
        float acc = 0.0f;
#pragma unroll
        for (int q = 0; q < 8; ++q) acc = fmaf(Cs[j * 8 + q], A[t * 64 + i * 8 + q], acc);
        g_veff[(((s * 32 + t) << 6) + (i * 8 + j)) * 64 + o] = 0.125f * acc;
    }
}

// ---------------------------------------------------------------------------
// main: grid = NSW * MTILES * KSPLIT = 512 CTAs, 256 threads, occ target 4/SM.
// CTA: 64 batches x 64 outputs, K = 128 (2 t's x 2 halves = 4 phases of 32 k),
// c-reduction fused into the load, double-buffered smem, software pipelined.
// ---------------------------------------------------------------------------
__global__ void __launch_bounds__(256, 4) main_kernel(const float* __restrict__ x) {
    __shared__ __align__(16) float xs[2][32][68];  // [buf][ij][b], pad 4 (STS 4-way max)
    __shared__ __align__(16) float ws[2][32][64];  // [buf][ij][o]

    const int tid = threadIdx.x;
    const int bx = blockIdx.x;
    const int ks = bx & 15;
    const int mt = (bx >> 4) & 15;
    const int s = bx >> 8;

    const int ijp = tid & 15, bb = tid >> 4;  // load map: ij = 2*ijp(+1), b = bb*4+u
    const int tx = tid & 15, ty = tid >> 4;   // compute map: o = 4tx.., b = 4ty..

    // x[b][time][ij]: b stride 32768 floats, time = s*256 + c*32 + t
    const float* xb = x + (size_t)(mt * 64 + bb * 4) * 32768 + (size_t)s * 16384 + 2 * ijp;

    u64 acc[2][4] = {};
    u64 xr[8];
    float4 wr0, wr1;

#define PH_T(ph) (ks * 2 + ((ph) >> 1))
#define PH_OFF(ph) ((size_t)(PH_T(ph)) * 64 + ((ph) & 1) * 32)

#define LDG_U(ph, u)                                                          \
    do {                                                                      \
        const u64* p = (const u64*)(xb + (size_t)(u) * 32768 + PH_OFF(ph));   \
        _Pragma("unroll") for (int c = 0; c < 8; ++c) xr[c] = p[c * 1024];    \
    } while (0)

#define STS_U(buf, u)                                                         \
    do {                                                                      \
        u64 s0 = add2(add2(xr[0], xr[1]), add2(xr[2], xr[3]));                \
        u64 s1 = add2(add2(xr[4], xr[5]), add2(xr[6], xr[7]));                \
        float2 v = up2(add2(s0, s1));                                         \
        xs[buf][2 * ijp][bb * 4 + (u)] = v.x;                                 \
        xs[buf][2 * ijp + 1][bb * 4 + (u)] = v.y;                             \
    } while (0)

#define LDG_W(ph)                                                             \
    do {                                                                      \
        const float4* wp = (const float4*)(g_veff +                          \
            (((size_t)s * 32 + PH_T(ph)) * 64 + ((ph) & 1) * 32) * 64);       \
        wr0 = wp[tid]; wr1 = wp[tid + 256];                                   \
    } while (0)

#define STS_W(buf)                                                            \
    do {                                                                      \
        float4* wd = (float4*)&ws[buf][0][0];                                 \
        wd[tid] = wr0; wd[tid + 256] = wr1;                                   \
    } while (0)

#define COMP8(buf, k0)                                                        \
    do {                                                                      \
        _Pragma("unroll") for (int k = (k0); k < (k0) + 8; ++k) {             \
            ulonglong2 xp = *(const ulonglong2*)&xs[buf][k][4 * ty];          \
            float4 wv = *(const float4*)&ws[buf][k][4 * tx];                  \
            u64 w0 = pk2(wv.x, wv.x), w1 = pk2(wv.y, wv.y);                   \
            u64 w2 = pk2(wv.z, wv.z), w3 = pk2(wv.w, wv.w);                   \
            fma2(acc[0][0], xp.x, w0); fma2(acc[1][0], xp.y, w0);             \
            fma2(acc[0][1], xp.x, w1); fma2(acc[1][1], xp.y, w1);             \
            fma2(acc[0][2], xp.x, w2); fma2(acc[1][2], xp.y, w2);             \
            fma2(acc[0][3], xp.x, w3); fma2(acc[1][3], xp.y, w3);             \
        }                                                                     \
    } while (0)

    // prologue: fill buffer 0 with phase 0
    LDG_W(0);
    LDG_U(0, 0); STS_U(0, 0);
    LDG_U(0, 1); STS_U(0, 1);
    LDG_U(0, 2); STS_U(0, 2);
    LDG_U(0, 3); STS_U(0, 3);
    STS_W(0);
    __syncthreads();

#pragma unroll
    for (int ph = 0; ph < 4; ++ph) {
        const int buf = ph & 1, nb = buf ^ 1;
        if (ph < 3) {
            LDG_W(ph + 1);
            LDG_U(ph + 1, 0); COMP8(buf, 0);  STS_U(nb, 0);
            LDG_U(ph + 1, 1); COMP8(buf, 8);  STS_U(nb, 1);
            LDG_U(ph + 1, 2); COMP8(buf, 16); STS_U(nb, 2);
            LDG_U(ph + 1, 3); COMP8(buf, 24); STS_U(nb, 3);
            STS_W(nb);
        } else {
            COMP8(buf, 0); COMP8(buf, 8); COMP8(buf, 16); COMP8(buf, 24);
        }
        __syncthreads();
    }

    // write partials: g_part[ks][b][s*64+o], float4 per row
    const int b0 = mt * 64 + 4 * ty;
    const int obase = s * 64 + 4 * tx;
#pragma unroll
    for (int p = 0; p < 2; ++p) {
        float2 c0 = up2(acc[p][0]), c1 = up2(acc[p][1]);
        float2 c2 = up2(acc[p][2]), c3 = up2(acc[p][3]);
        float4 r0 = make_float4(c0.x, c1.x, c2.x, c3.x);
        float4 r1 = make_float4(c0.y, c1.y, c2.y, c3.y);
        *(float4*)(g_part + ((size_t)ks << 17) + (size_t)(b0 + 2 * p) * 128 + obase) = r0;
        *(float4*)(g_part + ((size_t)ks << 17) + (size_t)(b0 + 2 * p + 1) * 128 + obase) = r1;
    }
}

// ---------------------------------------------------------------------------
// epilogue: sum KSPLIT partials + bias, LeakyReLU
// ---------------------------------------------------------------------------
__global__ void __launch_bounds__(256) epi_kernel(const float* __restrict__ bias,
                                                  float* __restrict__ out) {
    const int idx = blockIdx.x * 256 + threadIdx.x;  // < 131072
    float a = bias[idx & 127];
#pragma unroll
    for (int k = 0; k < KSPLIT; ++k) a += g_part[((size_t)k << 17) + idx];
    out[idx] = (a >= 0.0f) ? a : 0.02f * a;
}

// ---------------------------------------------------------------------------
extern "C" void kernel_launch(void* const* d_in, const int* in_sizes, int n_in,
                              void* d_out, int out_size) {
    const float* x = nullptr;
    const float* W = nullptr;
    const float* bias = nullptr;
    for (int i = 0; i < n_in; ++i) {
        if (in_sizes[i] == 1024 * 512 * 64) x = (const float*)d_in[i];
        else if (in_sizes[i] == NSW * NF * 32 * 64) W = (const float*)d_in[i];
        else if (in_sizes[i] == NSW * NF) bias = (const float*)d_in[i];
    }
    if (!x) x = (const float*)d_in[0];
    if (!W) W = (const float*)d_in[1];
    if (!bias) bias = (const float*)d_in[2];

    prep_kernel<<<NSW * NF, 256>>>(W);
    main_kernel<<<NSW * MTILES * KSPLIT, 256>>>(x);
    epi_kernel<<<(1024 * NSW * NF) / 256, 256>>>(bias, (float*)d_out);
}